// round 16
// baseline (speedup 1.0000x reference)
#include <cuda_runtime.h>
#include <cuda_fp16.h>
#include <math.h>
#include <stdint.h>

// GPT-2 stack: L=8, E=1024, H=16, T=2048, B=1, DH=64, fp32 in/out.
#define TT 2048
#define EE 1024
#define NH 16
#define HD 64
#define NL 8

// ---------------- scratch (device globals; no allocation allowed) ----------
__device__ float  g_h  [TT * EE];        // residual stream (fp32)
__device__ __half g_y  [TT * EE];        // LN output (fp16)
__device__ __half g_qkv[TT * 3 * EE];    // QKV (fp16)
__device__ __half g_att[TT * EE];        // attention output (fp16)
__device__ __half g_m1 [TT * 4 * EE];    // MLP hidden (fp16)

// transposed fp16 weights: wT[n][k]
__device__ __half g_wqkvT[NL * 3 * EE * EE];
__device__ __half g_wprojT[NL * EE * EE];
__device__ __half g_wfcT [NL * 4 * EE * EE];
__device__ __half g_wfc2T[NL * EE * 4 * EE];

// ---------------- helpers ----------------------------------------------------
__device__ __forceinline__ uint32_t smem_u32(const void* p) {
    return (uint32_t)__cvta_generic_to_shared(p);
}
__device__ __forceinline__ void mma_f16(float c[4], const uint32_t a[4],
                                        uint32_t b0, uint32_t b1) {
    asm volatile(
        "mma.sync.aligned.m16n8k16.row.col.f32.f16.f16.f32 "
        "{%0,%1,%2,%3}, {%4,%5,%6,%7}, {%8,%9}, {%0,%1,%2,%3};\n"
        : "+f"(c[0]), "+f"(c[1]), "+f"(c[2]), "+f"(c[3])
        : "r"(a[0]), "r"(a[1]), "r"(a[2]), "r"(a[3]), "r"(b0), "r"(b1));
}
__device__ __forceinline__ uint4 ldmx4(uint32_t a) {
    uint4 r;
    asm volatile("ldmatrix.sync.aligned.m8n8.x4.shared.b16 {%0,%1,%2,%3}, [%4];"
        : "=r"(r.x), "=r"(r.y), "=r"(r.z), "=r"(r.w) : "r"(a));
    return r;
}
__device__ __forceinline__ uint2 ldmx2t(uint32_t a) {
    uint2 r;
    asm volatile("ldmatrix.sync.aligned.m8n8.x2.trans.shared.b16 {%0,%1}, [%2];"
        : "=r"(r.x), "=r"(r.y) : "r"(a));
    return r;
}
#define CP16(dst, src) asm volatile("cp.async.cg.shared.global [%0], [%1], 16;\n" :: "r"(dst), "l"(src))
#define CP_COMMIT()    asm volatile("cp.async.commit_group;\n")
#define CP_WAIT(n)     asm volatile("cp.async.wait_group %0;\n" :: "n"(n))

// Programmatic dependent launch (sm_90+). Trigger is placed AFTER all global
// stores; wait is the first instruction before any dependent read.
#define GDC_WAIT()   asm volatile("griddepcontrol.wait;" ::: "memory")
#define GDC_LAUNCH() asm volatile("griddepcontrol.launch_dependents;" ::: "memory")

__device__ __forceinline__ float gelu_tanh(float x) {
    const float c0 = 0.7978845608028654f;   // sqrt(2/pi)
    float t = tanhf(c0 * (x + 0.044715f * x * x * x));
    return 0.5f * x * (1.0f + t);
}

// ---------------- transpose weights to fp16 [N][K] ---------------------------
__global__ __launch_bounds__(256) void transpose_half_kernel(
    const float* __restrict__ src, __half* __restrict__ dst, int K, int N)
{
    __shared__ float tile[32][33];
    const float* s = src + (size_t)blockIdx.z * K * N;
    __half* d = dst + (size_t)blockIdx.z * K * N;
    const int k0 = blockIdx.y * 32, n0 = blockIdx.x * 32;
    const int tx = threadIdx.x, ty = threadIdx.y;   // 32 x 8
    #pragma unroll
    for (int i = 0; i < 32; i += 8)
        tile[ty + i][tx] = s[(size_t)(k0 + ty + i) * N + n0 + tx];
    __syncthreads();
    #pragma unroll
    for (int i = 0; i < 32; i += 8)
        d[(size_t)(n0 + ty + i) * K + k0 + tx] = __float2half(tile[tx][ty + i]);
}

// ---------------- LayerNorm: one block per token row ------------------------
__global__ __launch_bounds__(256) void ln_kernel(
    const float* __restrict__ h, const float* __restrict__ w,
    const float* __restrict__ b, __half* __restrict__ y)
{
    GDC_WAIT();
    const int row = blockIdx.x;
    const int tid = threadIdx.x;
    const float4* hr = reinterpret_cast<const float4*>(h + (size_t)row * EE);
    float4 v = hr[tid];
    float s  = v.x + v.y + v.z + v.w;
    float sq = v.x*v.x + v.y*v.y + v.z*v.z + v.w*v.w;

    __shared__ float ss[8], ssq[8];
    #pragma unroll
    for (int off = 16; off > 0; off >>= 1) {
        s  += __shfl_xor_sync(0xffffffffu, s,  off);
        sq += __shfl_xor_sync(0xffffffffu, sq, off);
    }
    int lane = tid & 31, wid = tid >> 5;
    if (lane == 0) { ss[wid] = s; ssq[wid] = sq; }
    __syncthreads();
    if (tid == 0) {
        float S = 0.f, Q = 0.f;
        #pragma unroll
        for (int i = 0; i < 8; i++) { S += ss[i]; Q += ssq[i]; }
        ss[0] = S; ssq[0] = Q;
    }
    __syncthreads();
    const float mu  = ss[0] * (1.0f / EE);
    const float var = ssq[0] * (1.0f / EE) - mu * mu;
    const float inv = rsqrtf(var + 1e-5f);

    float4 wv = reinterpret_cast<const float4*>(w)[tid];
    float4 bv = reinterpret_cast<const float4*>(b)[tid];
    __half2* yr = reinterpret_cast<__half2*>(y + (size_t)row * EE);
    yr[tid*2]   = __floats2half2_rn((v.x - mu) * inv * wv.x + bv.x,
                                    (v.y - mu) * inv * wv.y + bv.y);
    yr[tid*2+1] = __floats2half2_rn((v.z - mu) * inv * wv.z + bv.z,
                                    (v.w - mu) * inv * wv.w + bv.w);

    GDC_LAUNCH();
}

// ---------------- fp16 tensor-core GEMM: 64x64 warp tiles, 2-stage -----------
// R12/R15 mainloop unchanged. MODE 2 now takes separate Cin (read) and Cv
// (write) so the final layer can emit fp32 directly into d_out.
// MODE 0: fp16(x+bias); MODE 1: fp16(gelu(x+bias)); MODE 2: Cout = Cin + x + bias.
template <int MODE, int BN>
__global__ __launch_bounds__(128, BN == 64 ? 4 : 2) void mma_gemm(
    const __half* __restrict__ A, const __half* __restrict__ Bt,
    const float* __restrict__ bias, void* __restrict__ Cv,
    const float* __restrict__ Cin,
    int M, int N, int K)
{
    constexpr int NT  = BN / 16;       // n8 tiles per warp (warp covers BN/2)
    constexpr int NP  = NT / 2;        // x4-ldmatrix n16 groups per warp
    constexpr int ASZ = 128 * 72;
    constexpr int BSZ = BN * 72;

    extern __shared__ __half smh[];
    const uint32_t base = smem_u32(smh);
    const uint32_t a_s[2] = { base,            base + (ASZ + BSZ) * 2 };
    const uint32_t b_s[2] = { base + ASZ * 2,  base + (2*ASZ + BSZ) * 2 };

    const int tid  = threadIdx.x;
    const int lane = tid & 31;
    const int warp = tid >> 5;          // 0..3
    const int wm   = (warp & 1) * 64;
    const int wn   = (warp >> 1) * (BN/2);
    const int g    = lane >> 2;
    const int tk   = lane & 3;

    const int bm = blockIdx.y * 128;
    const int bn = blockIdx.x * BN;

    const uint32_t aoff = (uint32_t)(wm + (lane & 15)) * 144u + (uint32_t)(lane >> 4) * 16u;
    const uint32_t boff = (uint32_t)(wn + (lane >> 4) * 8 + (lane & 7)) * 144u
                        + (uint32_t)((lane >> 3) & 1) * 16u;

    float acc[4][NT][4];
    #pragma unroll
    for (int mt = 0; mt < 4; mt++)
        #pragma unroll
        for (int nt = 0; nt < NT; nt++)
            #pragma unroll
            for (int i = 0; i < 4; i++) acc[mt][nt][i] = 0.f;

    auto load_tile = [&](int buf, int k0) {
        #pragma unroll
        for (int i = 0; i < 8; i++) {                   // A: 128 rows x 8 chunks
            int idx = tid + 128 * i;
            int r = idx >> 3, c = idx & 7;
            CP16(a_s[buf] + (uint32_t)(r * 144 + c * 16),
                 A + (size_t)(bm + r) * K + k0 + c * 8);
        }
        #pragma unroll
        for (int i = 0; i < BN / 16; i++) {             // B: BN rows x 8 chunks
            int idx = tid + 128 * i;
            int r = idx >> 3, c = idx & 7;
            CP16(b_s[buf] + (uint32_t)(r * 144 + c * 16),
                 Bt + (size_t)(bn + r) * K + k0 + c * 8);
        }
        CP_COMMIT();
    };

    GDC_WAIT();                // inputs (A, and Cin for MODE 2) valid past here

    const int nk = K / 64;
    load_tile(0, 0);

    for (int t = 0; t < nk; t++) {
        const int buf = t & 1;
        CP_WAIT(0);            // stage t resident (issuing warp)
        __syncthreads();       // all warps: stage t visible, stage t-1 consumed
        if (t + 1 < nk) load_tile(buf ^ 1, (t + 1) * 64);

        #pragma unroll
        for (int kb = 0; kb < 4; kb++) {
            uint4 bq[NP];
            #pragma unroll
            for (int np = 0; np < NP; np++)
                bq[np] = ldmx4(b_s[buf] + boff + (uint32_t)np * 2304u + kb * 32);
            #pragma unroll
            for (int mt = 0; mt < 4; mt++) {
                uint4 aq = ldmx4(a_s[buf] + aoff + (uint32_t)mt * 2304u + kb * 32);
                const uint32_t a[4] = { aq.x, aq.y, aq.z, aq.w };
                #pragma unroll
                for (int np = 0; np < NP; np++) {
                    mma_f16(acc[mt][2*np],   a, bq[np].x, bq[np].y);
                    mma_f16(acc[mt][2*np+1], a, bq[np].z, bq[np].w);
                }
            }
        }
    }

    #pragma unroll
    for (int mt = 0; mt < 4; mt++) {
        const int row0 = bm + wm + mt * 16 + g;
        #pragma unroll
        for (int nt = 0; nt < NT; nt++) {
            const int col = bn + wn + nt * 8 + 2 * tk;
            float2 bv = *reinterpret_cast<const float2*>(bias + col);
            float o0 = acc[mt][nt][0] + bv.x;
            float o1 = acc[mt][nt][1] + bv.y;
            float o2 = acc[mt][nt][2] + bv.x;
            float o3 = acc[mt][nt][3] + bv.y;
            if (MODE == 0) {
                __half* Ch = (__half*)Cv;
                *reinterpret_cast<__half2*>(Ch + (size_t)row0 * N + col)       = __floats2half2_rn(o0, o1);
                *reinterpret_cast<__half2*>(Ch + (size_t)(row0 + 8) * N + col) = __floats2half2_rn(o2, o3);
            } else if (MODE == 1) {
                __half* Ch = (__half*)Cv;
                *reinterpret_cast<__half2*>(Ch + (size_t)row0 * N + col) =
                    __floats2half2_rn(gelu_tanh(o0), gelu_tanh(o1));
                *reinterpret_cast<__half2*>(Ch + (size_t)(row0 + 8) * N + col) =
                    __floats2half2_rn(gelu_tanh(o2), gelu_tanh(o3));
            } else {
                float* Cf = (float*)Cv;
                const float* q0p = Cin + (size_t)row0 * N + col;
                const float* q1p = Cin + (size_t)(row0 + 8) * N + col;
                float2 c0 = *reinterpret_cast<const float2*>(q0p);
                float2 c1 = *reinterpret_cast<const float2*>(q1p);
                *reinterpret_cast<float2*>(Cf + (size_t)row0 * N + col) =
                    make_float2(o0 + c0.x, o1 + c0.y);
                *reinterpret_cast<float2*>(Cf + (size_t)(row0 + 8) * N + col) =
                    make_float2(o2 + c1.x, o3 + c1.y);
            }
        }
    }

    GDC_LAUNCH();              // AFTER all stores
}

// ---------------- fp16 flash attention: BQ=64, 4 warps, single wave ----------
#define BQ 64
#define BKV 64
#define ATT_SMEM ((64*72 + 64*72 + 2*2*64*72) * 2)   // 55296 bytes
#define LOG2E 1.4426950408889634f

__global__ __launch_bounds__(128, 4) void flash_attn_tc(
    const __half* __restrict__ qkv, __half* __restrict__ att)
{
    extern __shared__ __half smh[];
    __half* Qs  = smh;                   // [64][72]
    __half* Ps  = Qs + 64 * 72;          // [64][72]
    __half* KV0 = Ps + 64 * 72;          // 2 x (K[64][72], V[64][72])

    GDC_WAIT();                          // qkv complete past here

    const int qb = gridDim.x - 1 - blockIdx.x;   // heavy tiles first
    const int h  = blockIdx.y;
    const int q0 = qb * BQ;
    const int tid = threadIdx.x, lane = tid & 31, w = tid >> 5;   // w: 0..3
    const int g = lane >> 2, tk = lane & 3;
    const int ld = 3 * EE;
    const int qoff = h * HD;

    for (int i = tid; i < 64 * 8; i += 128) {
        int r = i >> 3, c = i & 7;
        *reinterpret_cast<uint4*>(Qs + r * 72 + c * 8) =
            *reinterpret_cast<const uint4*>(qkv + (size_t)(q0 + r) * ld + qoff + c * 8);
    }

    const uint32_t QsB = smem_u32(Qs);
    const uint32_t PsB = smem_u32(Ps);
    const uint32_t KVB = smem_u32(KV0);

    auto loadKV = [&](int buf, int k0) {
        const uint32_t kb_ = KVB + (uint32_t)buf * (2 * 64 * 72 * 2);
        const uint32_t vb_ = kb_ + 64 * 72 * 2;
        #pragma unroll
        for (int i = 0; i < 8; i++) {
            int idx = tid + 128 * i;           // 1024 chunks: 512 K + 512 V
            int sel = idx >> 9;
            int r = (idx >> 3) & 63, c = idx & 7;
            CP16((sel ? vb_ : kb_) + (uint32_t)(r * 144 + c * 16),
                 qkv + (size_t)(k0 + r) * ld + (1 + sel) * EE + qoff + c * 8);
        }
        CP_COMMIT();
    };

    const int kbmax = (q0 + BQ - 1) >> 6;   // inclusive == qb
    loadKV(0, 0);

    float O[8][4];
    float mrow[2] = { -1e30f, -1e30f };     // log2-domain running max
    float lrow[2] = { 0.f, 0.f };
    #pragma unroll
    for (int nt = 0; nt < 8; nt++)
        #pragma unroll
        for (int i = 0; i < 4; i++) O[nt][i] = 0.f;

    const uint32_t qoff_a = (uint32_t)(w * 16 + (lane & 15)) * 144u + (uint32_t)(lane >> 4) * 16u;
    const uint32_t koff_b = (uint32_t)((lane >> 4) * 8 + (lane & 7)) * 144u
                          + (uint32_t)((lane >> 3) & 1) * 16u;
    const uint32_t poff_a = PsB + (uint32_t)(w * 16 + (lane & 15)) * 144u
                          + (uint32_t)(lane >> 4) * 16u;
    __half* Pw = Ps + (w * 16) * 72;
    const float SCL2 = 0.125f * LOG2E;       // fold scale + log2(e)
    const float MASK2 = -10000.0f * LOG2E;

    for (int kb = 0; kb <= kbmax; kb++) {
        const int buf = kb & 1;
        CP_WAIT(0);
        __syncthreads();                                 // stage kb visible, kb-1 consumed
        if (kb < kbmax) loadKV(buf ^ 1, (kb + 1) * BKV);

        const uint32_t KsB = KVB + (uint32_t)buf * (2 * 64 * 72 * 2);
        const uint32_t VsB = KsB + 64 * 72 * 2;
        const int k0 = kb * BKV;

        // ---- S = Q @ K^T ----
        float S[8][4];
        #pragma unroll
        for (int nt = 0; nt < 8; nt++)
            #pragma unroll
            for (int i = 0; i < 4; i++) S[nt][i] = 0.f;

        #pragma unroll
        for (int kk = 0; kk < 4; kk++) {
            uint4 aq = ldmx4(QsB + qoff_a + kk * 32);
            const uint32_t a[4] = { aq.x, aq.y, aq.z, aq.w };
            #pragma unroll
            for (int np = 0; np < 4; np++) {
                uint4 bq = ldmx4(KsB + koff_b + (uint32_t)np * 2304u + kk * 32);
                mma_f16(S[2*np],   a, bq.x, bq.y);
                mma_f16(S[2*np+1], a, bq.z, bq.w);
            }
        }

        // ---- scale(log2-domain) + causal mask + online softmax ----
        #pragma unroll
        for (int hf = 0; hf < 2; hf++) {
            const int gq = q0 + w * 16 + g + hf * 8;
            #pragma unroll
            for (int nt = 0; nt < 8; nt++) {
                const int gk = k0 + nt * 8 + 2 * tk;
                float s0 = S[nt][hf*2]   * SCL2;
                float s1 = S[nt][hf*2+1] * SCL2;
                S[nt][hf*2]   = (gk     <= gq) ? s0 : MASK2;
                S[nt][hf*2+1] = (gk + 1 <= gq) ? s1 : MASK2;
            }
            float rm = -1e30f;
            #pragma unroll
            for (int nt = 0; nt < 8; nt++)
                rm = fmaxf(rm, fmaxf(S[nt][hf*2], S[nt][hf*2+1]));
            rm = fmaxf(rm, __shfl_xor_sync(0xffffffffu, rm, 1));
            rm = fmaxf(rm, __shfl_xor_sync(0xffffffffu, rm, 2));
            const float mn = fmaxf(mrow[hf], rm);
            const float corr = exp2f(mrow[hf] - mn);
            mrow[hf] = mn;
            float rs = 0.f;
            #pragma unroll
            for (int nt = 0; nt < 8; nt++) {
                float p0 = exp2f(S[nt][hf*2]   - mn);
                float p1 = exp2f(S[nt][hf*2+1] - mn);
                S[nt][hf*2] = p0; S[nt][hf*2+1] = p1;
                rs += p0 + p1;
            }
            rs += __shfl_xor_sync(0xffffffffu, rs, 1);
            rs += __shfl_xor_sync(0xffffffffu, rs, 2);
            lrow[hf] = lrow[hf] * corr + rs;
            #pragma unroll
            for (int nt = 0; nt < 8; nt++) {
                O[nt][hf*2] *= corr; O[nt][hf*2+1] *= corr;
            }
        }

        // ---- stage P as fp16 (per-warp region) ----
        #pragma unroll
        for (int nt = 0; nt < 8; nt++) {
            *reinterpret_cast<__half2*>(Pw + (g    ) * 72 + nt * 8 + 2 * tk) =
                __floats2half2_rn(S[nt][0], S[nt][1]);
            *reinterpret_cast<__half2*>(Pw + (g + 8) * 72 + nt * 8 + 2 * tk) =
                __floats2half2_rn(S[nt][2], S[nt][3]);
        }
        __syncwarp();

        // ---- O += P @ V ----
        #pragma unroll
        for (int kk = 0; kk < 4; kk++) {
            uint4 ap = ldmx4(poff_a + kk * 32);
            const uint32_t a[4] = { ap.x, ap.y, ap.z, ap.w };
            const uint32_t vrow = VsB + (uint32_t)(kk * 16 + (lane & 15)) * 144u;
            #pragma unroll
            for (int nt = 0; nt < 8; nt++) {
                uint2 bv = ldmx2t(vrow + nt * 16);
                mma_f16(O[nt], a, bv.x, bv.y);
            }
        }
    }

    const float inv0 = 1.0f / lrow[0];
    const float inv1 = 1.0f / lrow[1];
    const int r0 = q0 + w * 16 + g;
    #pragma unroll
    for (int nt = 0; nt < 8; nt++) {
        const int col = qoff + nt * 8 + 2 * tk;
        *reinterpret_cast<__half2*>(att + (size_t)r0 * EE + col) =
            __floats2half2_rn(O[nt][0] * inv0, O[nt][1] * inv0);
        *reinterpret_cast<__half2*>(att + (size_t)(r0 + 8) * EE + col) =
            __floats2half2_rn(O[nt][2] * inv1, O[nt][3] * inv1);
    }

    GDC_LAUNCH();              // AFTER all stores
}

// ---------------- host orchestration ---------------------------------------
extern "C" void kernel_launch(void* const* d_in, const int* in_sizes, int n_in,
                              void* d_out, int out_size)
{
    const float* x      = (const float*)d_in[0];
    const float* ln1_w  = (const float*)d_in[1];
    const float* ln1_b  = (const float*)d_in[2];
    const float* attn_w = (const float*)d_in[3];
    const float* attn_b = (const float*)d_in[4];
    const float* proj_w = (const float*)d_in[5];
    const float* proj_b = (const float*)d_in[6];
    const float* ln2_w  = (const float*)d_in[7];
    const float* ln2_b  = (const float*)d_in[8];
    const float* fc_w   = (const float*)d_in[9];
    const float* fc_b   = (const float*)d_in[10];
    const float* fc2_w  = (const float*)d_in[11];
    const float* fc2_b  = (const float*)d_in[12];

    float *h;
    __half *y, *qkv, *att, *m1, *wqkvT, *wprojT, *wfcT, *wfc2T;
    cudaGetSymbolAddress((void**)&h,     g_h);
    cudaGetSymbolAddress((void**)&y,     g_y);
    cudaGetSymbolAddress((void**)&qkv,   g_qkv);
    cudaGetSymbolAddress((void**)&att,   g_att);
    cudaGetSymbolAddress((void**)&m1,    g_m1);
    cudaGetSymbolAddress((void**)&wqkvT, g_wqkvT);
    cudaGetSymbolAddress((void**)&wprojT,g_wprojT);
    cudaGetSymbolAddress((void**)&wfcT,  g_wfcT);
    cudaGetSymbolAddress((void**)&wfc2T, g_wfc2T);

    constexpr int SMEM_128 = 2 * (128 + 128) * 144;   // 73728 B
    constexpr int SMEM_64  = 2 * (128 +  64) * 144;   // 55296 B
    cudaFuncSetAttribute(mma_gemm<0,64>,  cudaFuncAttributeMaxDynamicSharedMemorySize, SMEM_64);
    cudaFuncSetAttribute(mma_gemm<1,128>, cudaFuncAttributeMaxDynamicSharedMemorySize, SMEM_128);
    cudaFuncSetAttribute(mma_gemm<2,64>,  cudaFuncAttributeMaxDynamicSharedMemorySize, SMEM_64);
    cudaFuncSetAttribute(flash_attn_tc,   cudaFuncAttributeMaxDynamicSharedMemorySize, ATT_SMEM);

    // PDL launcher on the default stream
    auto pdl = [](auto kern, dim3 grid, dim3 block, size_t smem, auto... args) {
        cudaLaunchConfig_t cfg = {};
        cfg.gridDim = grid; cfg.blockDim = block;
        cfg.dynamicSmemBytes = smem; cfg.stream = 0;
        cudaLaunchAttribute attr[1];
        attr[0].id = cudaLaunchAttributeProgrammaticStreamSerialization;
        attr[0].val.programmaticStreamSerializationAllowed = 1;
        cfg.attrs = attr; cfg.numAttrs = 1;
        cudaLaunchKernelEx(&cfg, kern, args...);
    };

    // ---- side stream: weight transposes overlap layer-0 compute -------------
    cudaStream_t s2;
    cudaStreamCreateWithFlags(&s2, cudaStreamNonBlocking);
    cudaEvent_t evFork, evW0, evW1;
    cudaEventCreateWithFlags(&evFork, cudaEventDisableTiming);
    cudaEventCreateWithFlags(&evW0,   cudaEventDisableTiming);
    cudaEventCreateWithFlags(&evW1,   cudaEventDisableTiming);

    cudaEventRecord(evFork, 0);
    cudaStreamWaitEvent(s2, evFork, 0);

    const dim3 tb(32, 8);
    transpose_half_kernel<<<dim3(3*EE/32, EE/32, NL),   tb, 0, s2>>>(attn_w, wqkvT,  EE,   3*EE);
    cudaEventRecord(evW0, s2);                         // qkv weights ready
    transpose_half_kernel<<<dim3(EE/32,   EE/32, NL),   tb, 0, s2>>>(proj_w, wprojT, EE,   EE);
    transpose_half_kernel<<<dim3(4*EE/32, EE/32, NL),   tb, 0, s2>>>(fc_w,   wfcT,   EE,   4*EE);
    transpose_half_kernel<<<dim3(EE/32,   4*EE/32, NL), tb, 0, s2>>>(fc2_w,  wfc2T,  4*EE, EE);
    cudaEventRecord(evW1, s2);                         // all other weights ready

    cudaMemcpyAsync(h, x, (size_t)TT * EE * sizeof(float),
                    cudaMemcpyDeviceToDevice, 0);

    const dim3 blkG(128);                      // GEMM CTAs: 4 warps
    const dim3 blkA(128);                      // attention CTAs: 4 warps
    const dim3 blk(256);
    const dim3 gLN(TT);
    const dim3 gQKV(3 * EE / 64, TT / 128);    // (48,16) = 768 CTAs
    const dim3 gPROJ(EE / 64, TT / 128);       // (16,16)
    const dim3 gFC(4 * EE / 128, TT / 128);    // (32,16)
    const dim3 gFC2(EE / 64, TT / 128);        // (16,16)
    const dim3 gATT(TT / BQ, NH);              // (32,16) = 512 CTAs

    for (int lyr = 0; lyr < NL; lyr++) {
        const __half* aw  = wqkvT  + (size_t)lyr * EE * 3 * EE;
        const float*  ab  = attn_b + (size_t)lyr * 3 * EE;
        const __half* pw  = wprojT + (size_t)lyr * EE * EE;
        const float*  pb  = proj_b + (size_t)lyr * EE;
        const __half* fw  = wfcT   + (size_t)lyr * EE * 4 * EE;
        const float*  fb  = fc_b   + (size_t)lyr * 4 * EE;
        const __half* f2w = wfc2T  + (size_t)lyr * 4 * EE * EE;
        const float*  f2b = fc2_b  + (size_t)lyr * EE;

        // attn block
        pdl(ln_kernel, gLN, blk, 0,
            (const float*)h, (const float*)(ln1_w + (size_t)lyr * EE),
            (const float*)(ln1_b + (size_t)lyr * EE), (__half*)y);
        if (lyr == 0) cudaStreamWaitEvent(0, evW0, 0);          // wqkvT ready
        pdl(mma_gemm<0,64>, gQKV, blkG, (size_t)SMEM_64,
            (const __half*)y, aw, ab, (void*)qkv, (const float*)nullptr,
            (int)TT, (int)(3*EE), (int)EE);
        pdl(flash_attn_tc, gATT, blkA, (size_t)ATT_SMEM,
            (const __half*)qkv, (__half*)att);
        if (lyr == 0) cudaStreamWaitEvent(0, evW1, 0);          // remaining weights ready
        pdl(mma_gemm<2,64>, gPROJ, blkG, (size_t)SMEM_64,
            (const __half*)att, pw, pb, (void*)h, (const float*)h,
            (int)TT, (int)EE, (int)EE);

        // MLP block
        pdl(ln_kernel, gLN, blk, 0,
            (const float*)h, (const float*)(ln2_w + (size_t)lyr * EE),
            (const float*)(ln2_b + (size_t)lyr * EE), (__half*)y);
        pdl(mma_gemm<1,128>, gFC, blkG, (size_t)SMEM_128,
            (const __half*)y, fw, fb, (void*)m1, (const float*)nullptr,
            (int)TT, (int)(4*EE), (int)EE);
        // final layer: write residual result straight into d_out (fp32)
        float* c_out = (lyr == NL - 1) ? (float*)d_out : h;
        pdl(mma_gemm<2,64>, gFC2, blkG, (size_t)SMEM_64,
            (const __half*)m1, f2w, f2b, (void*)c_out, (const float*)h,
            (int)TT, (int)EE, (int)(4*EE));
    }
}

// round 17
// speedup vs baseline: 1.0819x; 1.0819x over previous
#include <cuda_runtime.h>
#include <cuda_fp16.h>
#include <math.h>
#include <stdint.h>

// GPT-2 stack: L=8, E=1024, H=16, T=2048, B=1, DH=64, fp32 in/out.
#define TT 2048
#define EE 1024
#define NH 16
#define HD 64
#define NL 8

// ---------------- scratch (device globals; no allocation allowed) ----------
__device__ float  g_h  [TT * EE];        // residual stream (fp32)
__device__ __half g_y  [TT * EE];        // LN output (fp16)
__device__ __half g_qkv[TT * 3 * EE];    // QKV (fp16)
__device__ __half g_att[TT * EE];        // attention output (fp16)
__device__ __half g_m1 [TT * 4 * EE];    // MLP hidden (fp16)

// transposed fp16 weights: wT[n][k]
__device__ __half g_wqkvT[NL * 3 * EE * EE];
__device__ __half g_wprojT[NL * EE * EE];
__device__ __half g_wfcT [NL * 4 * EE * EE];
__device__ __half g_wfc2T[NL * EE * 4 * EE];

// ---------------- helpers ----------------------------------------------------
__device__ __forceinline__ uint32_t smem_u32(const void* p) {
    return (uint32_t)__cvta_generic_to_shared(p);
}
__device__ __forceinline__ void mma_f16(float c[4], const uint32_t a[4],
                                        uint32_t b0, uint32_t b1) {
    asm volatile(
        "mma.sync.aligned.m16n8k16.row.col.f32.f16.f16.f32 "
        "{%0,%1,%2,%3}, {%4,%5,%6,%7}, {%8,%9}, {%0,%1,%2,%3};\n"
        : "+f"(c[0]), "+f"(c[1]), "+f"(c[2]), "+f"(c[3])
        : "r"(a[0]), "r"(a[1]), "r"(a[2]), "r"(a[3]), "r"(b0), "r"(b1));
}
__device__ __forceinline__ uint4 ldmx4(uint32_t a) {
    uint4 r;
    asm volatile("ldmatrix.sync.aligned.m8n8.x4.shared.b16 {%0,%1,%2,%3}, [%4];"
        : "=r"(r.x), "=r"(r.y), "=r"(r.z), "=r"(r.w) : "r"(a));
    return r;
}
__device__ __forceinline__ uint2 ldmx2t(uint32_t a) {
    uint2 r;
    asm volatile("ldmatrix.sync.aligned.m8n8.x2.trans.shared.b16 {%0,%1}, [%2];"
        : "=r"(r.x), "=r"(r.y) : "r"(a));
    return r;
}
#define CP16(dst, src) asm volatile("cp.async.cg.shared.global [%0], [%1], 16;\n" :: "r"(dst), "l"(src))
#define CP_COMMIT()    asm volatile("cp.async.commit_group;\n")
#define CP_WAIT(n)     asm volatile("cp.async.wait_group %0;\n" :: "n"(n))

// Programmatic dependent launch (sm_90+). Trigger is placed AFTER all global
// stores; wait is the first instruction before any dependent read.
#define GDC_WAIT()   asm volatile("griddepcontrol.wait;" ::: "memory")
#define GDC_LAUNCH() asm volatile("griddepcontrol.launch_dependents;" ::: "memory")

__device__ __forceinline__ float gelu_tanh(float x) {
    const float c0 = 0.7978845608028654f;   // sqrt(2/pi)
    float t = tanhf(c0 * (x + 0.044715f * x * x * x));
    return 0.5f * x * (1.0f + t);
}

// ---------------- transpose weights to fp16 [N][K] ---------------------------
__global__ __launch_bounds__(256) void transpose_half_kernel(
    const float* __restrict__ src, __half* __restrict__ dst, int K, int N)
{
    __shared__ float tile[32][33];
    const float* s = src + (size_t)blockIdx.z * K * N;
    __half* d = dst + (size_t)blockIdx.z * K * N;
    const int k0 = blockIdx.y * 32, n0 = blockIdx.x * 32;
    const int tx = threadIdx.x, ty = threadIdx.y;   // 32 x 8
    #pragma unroll
    for (int i = 0; i < 32; i += 8)
        tile[ty + i][tx] = s[(size_t)(k0 + ty + i) * N + n0 + tx];
    __syncthreads();
    #pragma unroll
    for (int i = 0; i < 32; i += 8)
        d[(size_t)(n0 + ty + i) * K + k0 + tx] = __float2half(tile[tx][ty + i]);
}

// ---------------- LayerNorm: one block per token row ------------------------
__global__ __launch_bounds__(256) void ln_kernel(
    const float* __restrict__ h, const float* __restrict__ w,
    const float* __restrict__ b, __half* __restrict__ y)
{
    GDC_WAIT();
    const int row = blockIdx.x;
    const int tid = threadIdx.x;
    const float4* hr = reinterpret_cast<const float4*>(h + (size_t)row * EE);
    float4 v = hr[tid];
    float s  = v.x + v.y + v.z + v.w;
    float sq = v.x*v.x + v.y*v.y + v.z*v.z + v.w*v.w;

    __shared__ float ss[8], ssq[8];
    #pragma unroll
    for (int off = 16; off > 0; off >>= 1) {
        s  += __shfl_xor_sync(0xffffffffu, s,  off);
        sq += __shfl_xor_sync(0xffffffffu, sq, off);
    }
    int lane = tid & 31, wid = tid >> 5;
    if (lane == 0) { ss[wid] = s; ssq[wid] = sq; }
    __syncthreads();
    if (tid == 0) {
        float S = 0.f, Q = 0.f;
        #pragma unroll
        for (int i = 0; i < 8; i++) { S += ss[i]; Q += ssq[i]; }
        ss[0] = S; ssq[0] = Q;
    }
    __syncthreads();
    const float mu  = ss[0] * (1.0f / EE);
    const float var = ssq[0] * (1.0f / EE) - mu * mu;
    const float inv = rsqrtf(var + 1e-5f);

    float4 wv = reinterpret_cast<const float4*>(w)[tid];
    float4 bv = reinterpret_cast<const float4*>(b)[tid];
    __half2* yr = reinterpret_cast<__half2*>(y + (size_t)row * EE);
    yr[tid*2]   = __floats2half2_rn((v.x - mu) * inv * wv.x + bv.x,
                                    (v.y - mu) * inv * wv.y + bv.y);
    yr[tid*2+1] = __floats2half2_rn((v.z - mu) * inv * wv.z + bv.z,
                                    (v.w - mu) * inv * wv.w + bv.w);

    GDC_LAUNCH();
}

// ---------------- fp16 tensor-core GEMM: 64x64 warp tiles, 2-stage -----------
// R15 configuration (occ 3 for BN=64). MODE 2 takes separate Cin (read) and
// Cv (write) so the final layer can emit fp32 directly into d_out.
// MODE 0: fp16(x+bias); MODE 1: fp16(gelu(x+bias)); MODE 2: Cout = Cin + x + bias.
template <int MODE, int BN>
__global__ __launch_bounds__(128, BN == 64 ? 3 : 2) void mma_gemm(
    const __half* __restrict__ A, const __half* __restrict__ Bt,
    const float* __restrict__ bias, void* __restrict__ Cv,
    const float* __restrict__ Cin,
    int M, int N, int K)
{
    constexpr int NT  = BN / 16;       // n8 tiles per warp (warp covers BN/2)
    constexpr int NP  = NT / 2;        // x4-ldmatrix n16 groups per warp
    constexpr int ASZ = 128 * 72;
    constexpr int BSZ = BN * 72;

    extern __shared__ __half smh[];
    const uint32_t base = smem_u32(smh);
    const uint32_t a_s[2] = { base,            base + (ASZ + BSZ) * 2 };
    const uint32_t b_s[2] = { base + ASZ * 2,  base + (2*ASZ + BSZ) * 2 };

    const int tid  = threadIdx.x;
    const int lane = tid & 31;
    const int warp = tid >> 5;          // 0..3
    const int wm   = (warp & 1) * 64;
    const int wn   = (warp >> 1) * (BN/2);
    const int g    = lane >> 2;
    const int tk   = lane & 3;

    const int bm = blockIdx.y * 128;
    const int bn = blockIdx.x * BN;

    const uint32_t aoff = (uint32_t)(wm + (lane & 15)) * 144u + (uint32_t)(lane >> 4) * 16u;
    const uint32_t boff = (uint32_t)(wn + (lane >> 4) * 8 + (lane & 7)) * 144u
                        + (uint32_t)((lane >> 3) & 1) * 16u;

    float acc[4][NT][4];
    #pragma unroll
    for (int mt = 0; mt < 4; mt++)
        #pragma unroll
        for (int nt = 0; nt < NT; nt++)
            #pragma unroll
            for (int i = 0; i < 4; i++) acc[mt][nt][i] = 0.f;

    auto load_tile = [&](int buf, int k0) {
        #pragma unroll
        for (int i = 0; i < 8; i++) {                   // A: 128 rows x 8 chunks
            int idx = tid + 128 * i;
            int r = idx >> 3, c = idx & 7;
            CP16(a_s[buf] + (uint32_t)(r * 144 + c * 16),
                 A + (size_t)(bm + r) * K + k0 + c * 8);
        }
        #pragma unroll
        for (int i = 0; i < BN / 16; i++) {             // B: BN rows x 8 chunks
            int idx = tid + 128 * i;
            int r = idx >> 3, c = idx & 7;
            CP16(b_s[buf] + (uint32_t)(r * 144 + c * 16),
                 Bt + (size_t)(bn + r) * K + k0 + c * 8);
        }
        CP_COMMIT();
    };

    GDC_WAIT();                // inputs (A, and Cin for MODE 2) valid past here

    const int nk = K / 64;
    load_tile(0, 0);

    for (int t = 0; t < nk; t++) {
        const int buf = t & 1;
        CP_WAIT(0);            // stage t resident (issuing warp)
        __syncthreads();       // all warps: stage t visible, stage t-1 consumed
        if (t + 1 < nk) load_tile(buf ^ 1, (t + 1) * 64);

        #pragma unroll
        for (int kb = 0; kb < 4; kb++) {
            uint4 bq[NP];
            #pragma unroll
            for (int np = 0; np < NP; np++)
                bq[np] = ldmx4(b_s[buf] + boff + (uint32_t)np * 2304u + kb * 32);
            #pragma unroll
            for (int mt = 0; mt < 4; mt++) {
                uint4 aq = ldmx4(a_s[buf] + aoff + (uint32_t)mt * 2304u + kb * 32);
                const uint32_t a[4] = { aq.x, aq.y, aq.z, aq.w };
                #pragma unroll
                for (int np = 0; np < NP; np++) {
                    mma_f16(acc[mt][2*np],   a, bq[np].x, bq[np].y);
                    mma_f16(acc[mt][2*np+1], a, bq[np].z, bq[np].w);
                }
            }
        }
    }

    #pragma unroll
    for (int mt = 0; mt < 4; mt++) {
        const int row0 = bm + wm + mt * 16 + g;
        #pragma unroll
        for (int nt = 0; nt < NT; nt++) {
            const int col = bn + wn + nt * 8 + 2 * tk;
            float2 bv = *reinterpret_cast<const float2*>(bias + col);
            float o0 = acc[mt][nt][0] + bv.x;
            float o1 = acc[mt][nt][1] + bv.y;
            float o2 = acc[mt][nt][2] + bv.x;
            float o3 = acc[mt][nt][3] + bv.y;
            if (MODE == 0) {
                __half* Ch = (__half*)Cv;
                *reinterpret_cast<__half2*>(Ch + (size_t)row0 * N + col)       = __floats2half2_rn(o0, o1);
                *reinterpret_cast<__half2*>(Ch + (size_t)(row0 + 8) * N + col) = __floats2half2_rn(o2, o3);
            } else if (MODE == 1) {
                __half* Ch = (__half*)Cv;
                *reinterpret_cast<__half2*>(Ch + (size_t)row0 * N + col) =
                    __floats2half2_rn(gelu_tanh(o0), gelu_tanh(o1));
                *reinterpret_cast<__half2*>(Ch + (size_t)(row0 + 8) * N + col) =
                    __floats2half2_rn(gelu_tanh(o2), gelu_tanh(o3));
            } else {
                float* Cf = (float*)Cv;
                const float* q0p = Cin + (size_t)row0 * N + col;
                const float* q1p = Cin + (size_t)(row0 + 8) * N + col;
                float2 c0 = *reinterpret_cast<const float2*>(q0p);
                float2 c1 = *reinterpret_cast<const float2*>(q1p);
                *reinterpret_cast<float2*>(Cf + (size_t)row0 * N + col) =
                    make_float2(o0 + c0.x, o1 + c0.y);
                *reinterpret_cast<float2*>(Cf + (size_t)(row0 + 8) * N + col) =
                    make_float2(o2 + c1.x, o3 + c1.y);
            }
        }
    }

    GDC_LAUNCH();              // AFTER all stores
}

// ---------------- fp16 flash attention: BQ=64, 4 warps, occ 3 (R15) ----------
#define BQ 64
#define BKV 64
#define ATT_SMEM ((64*72 + 64*72 + 2*2*64*72) * 2)   // 55296 bytes
#define LOG2E 1.4426950408889634f

__global__ __launch_bounds__(128, 3) void flash_attn_tc(
    const __half* __restrict__ qkv, __half* __restrict__ att)
{
    extern __shared__ __half smh[];
    __half* Qs  = smh;                   // [64][72]
    __half* Ps  = Qs + 64 * 72;          // [64][72]
    __half* KV0 = Ps + 64 * 72;          // 2 x (K[64][72], V[64][72])

    GDC_WAIT();                          // qkv complete past here

    const int qb = gridDim.x - 1 - blockIdx.x;   // heavy tiles first
    const int h  = blockIdx.y;
    const int q0 = qb * BQ;
    const int tid = threadIdx.x, lane = tid & 31, w = tid >> 5;   // w: 0..3
    const int g = lane >> 2, tk = lane & 3;
    const int ld = 3 * EE;
    const int qoff = h * HD;

    for (int i = tid; i < 64 * 8; i += 128) {
        int r = i >> 3, c = i & 7;
        *reinterpret_cast<uint4*>(Qs + r * 72 + c * 8) =
            *reinterpret_cast<const uint4*>(qkv + (size_t)(q0 + r) * ld + qoff + c * 8);
    }

    const uint32_t QsB = smem_u32(Qs);
    const uint32_t PsB = smem_u32(Ps);
    const uint32_t KVB = smem_u32(KV0);

    auto loadKV = [&](int buf, int k0) {
        const uint32_t kb_ = KVB + (uint32_t)buf * (2 * 64 * 72 * 2);
        const uint32_t vb_ = kb_ + 64 * 72 * 2;
        #pragma unroll
        for (int i = 0; i < 8; i++) {
            int idx = tid + 128 * i;           // 1024 chunks: 512 K + 512 V
            int sel = idx >> 9;
            int r = (idx >> 3) & 63, c = idx & 7;
            CP16((sel ? vb_ : kb_) + (uint32_t)(r * 144 + c * 16),
                 qkv + (size_t)(k0 + r) * ld + (1 + sel) * EE + qoff + c * 8);
        }
        CP_COMMIT();
    };

    const int kbmax = (q0 + BQ - 1) >> 6;   // inclusive == qb
    loadKV(0, 0);

    float O[8][4];
    float mrow[2] = { -1e30f, -1e30f };     // log2-domain running max
    float lrow[2] = { 0.f, 0.f };
    #pragma unroll
    for (int nt = 0; nt < 8; nt++)
        #pragma unroll
        for (int i = 0; i < 4; i++) O[nt][i] = 0.f;

    const uint32_t qoff_a = (uint32_t)(w * 16 + (lane & 15)) * 144u + (uint32_t)(lane >> 4) * 16u;
    const uint32_t koff_b = (uint32_t)((lane >> 4) * 8 + (lane & 7)) * 144u
                          + (uint32_t)((lane >> 3) & 1) * 16u;
    const uint32_t poff_a = PsB + (uint32_t)(w * 16 + (lane & 15)) * 144u
                          + (uint32_t)(lane >> 4) * 16u;
    __half* Pw = Ps + (w * 16) * 72;
    const float SCL2 = 0.125f * LOG2E;       // fold scale + log2(e)
    const float MASK2 = -10000.0f * LOG2E;

    for (int kb = 0; kb <= kbmax; kb++) {
        const int buf = kb & 1;
        CP_WAIT(0);
        __syncthreads();                                 // stage kb visible, kb-1 consumed
        if (kb < kbmax) loadKV(buf ^ 1, (kb + 1) * BKV);

        const uint32_t KsB = KVB + (uint32_t)buf * (2 * 64 * 72 * 2);
        const uint32_t VsB = KsB + 64 * 72 * 2;
        const int k0 = kb * BKV;

        // ---- S = Q @ K^T ----
        float S[8][4];
        #pragma unroll
        for (int nt = 0; nt < 8; nt++)
            #pragma unroll
            for (int i = 0; i < 4; i++) S[nt][i] = 0.f;

        #pragma unroll
        for (int kk = 0; kk < 4; kk++) {
            uint4 aq = ldmx4(QsB + qoff_a + kk * 32);
            const uint32_t a[4] = { aq.x, aq.y, aq.z, aq.w };
            #pragma unroll
            for (int np = 0; np < 4; np++) {
                uint4 bq = ldmx4(KsB + koff_b + (uint32_t)np * 2304u + kk * 32);
                mma_f16(S[2*np],   a, bq.x, bq.y);
                mma_f16(S[2*np+1], a, bq.z, bq.w);
            }
        }

        // ---- scale(log2-domain) + causal mask + online softmax ----
        #pragma unroll
        for (int hf = 0; hf < 2; hf++) {
            const int gq = q0 + w * 16 + g + hf * 8;
            #pragma unroll
            for (int nt = 0; nt < 8; nt++) {
                const int gk = k0 + nt * 8 + 2 * tk;
                float s0 = S[nt][hf*2]   * SCL2;
                float s1 = S[nt][hf*2+1] * SCL2;
                S[nt][hf*2]   = (gk     <= gq) ? s0 : MASK2;
                S[nt][hf*2+1] = (gk + 1 <= gq) ? s1 : MASK2;
            }
            float rm = -1e30f;
            #pragma unroll
            for (int nt = 0; nt < 8; nt++)
                rm = fmaxf(rm, fmaxf(S[nt][hf*2], S[nt][hf*2+1]));
            rm = fmaxf(rm, __shfl_xor_sync(0xffffffffu, rm, 1));
            rm = fmaxf(rm, __shfl_xor_sync(0xffffffffu, rm, 2));
            const float mn = fmaxf(mrow[hf], rm);
            const float corr = exp2f(mrow[hf] - mn);
            mrow[hf] = mn;
            float rs = 0.f;
            #pragma unroll
            for (int nt = 0; nt < 8; nt++) {
                float p0 = exp2f(S[nt][hf*2]   - mn);
                float p1 = exp2f(S[nt][hf*2+1] - mn);
                S[nt][hf*2] = p0; S[nt][hf*2+1] = p1;
                rs += p0 + p1;
            }
            rs += __shfl_xor_sync(0xffffffffu, rs, 1);
            rs += __shfl_xor_sync(0xffffffffu, rs, 2);
            lrow[hf] = lrow[hf] * corr + rs;
            #pragma unroll
            for (int nt = 0; nt < 8; nt++) {
                O[nt][hf*2] *= corr; O[nt][hf*2+1] *= corr;
            }
        }

        // ---- stage P as fp16 (per-warp region) ----
        #pragma unroll
        for (int nt = 0; nt < 8; nt++) {
            *reinterpret_cast<__half2*>(Pw + (g    ) * 72 + nt * 8 + 2 * tk) =
                __floats2half2_rn(S[nt][0], S[nt][1]);
            *reinterpret_cast<__half2*>(Pw + (g + 8) * 72 + nt * 8 + 2 * tk) =
                __floats2half2_rn(S[nt][2], S[nt][3]);
        }
        __syncwarp();

        // ---- O += P @ V ----
        #pragma unroll
        for (int kk = 0; kk < 4; kk++) {
            uint4 ap = ldmx4(poff_a + kk * 32);
            const uint32_t a[4] = { ap.x, ap.y, ap.z, ap.w };
            const uint32_t vrow = VsB + (uint32_t)(kk * 16 + (lane & 15)) * 144u;
            #pragma unroll
            for (int nt = 0; nt < 8; nt++) {
                uint2 bv = ldmx2t(vrow + nt * 16);
                mma_f16(O[nt], a, bv.x, bv.y);
            }
        }
    }

    const float inv0 = 1.0f / lrow[0];
    const float inv1 = 1.0f / lrow[1];
    const int r0 = q0 + w * 16 + g;
    #pragma unroll
    for (int nt = 0; nt < 8; nt++) {
        const int col = qoff + nt * 8 + 2 * tk;
        *reinterpret_cast<__half2*>(att + (size_t)r0 * EE + col) =
            __floats2half2_rn(O[nt][0] * inv0, O[nt][1] * inv0);
        *reinterpret_cast<__half2*>(att + (size_t)(r0 + 8) * EE + col) =
            __floats2half2_rn(O[nt][2] * inv1, O[nt][3] * inv1);
    }

    GDC_LAUNCH();              // AFTER all stores
}

// ---------------- host orchestration ---------------------------------------
extern "C" void kernel_launch(void* const* d_in, const int* in_sizes, int n_in,
                              void* d_out, int out_size)
{
    const float* x      = (const float*)d_in[0];
    const float* ln1_w  = (const float*)d_in[1];
    const float* ln1_b  = (const float*)d_in[2];
    const float* attn_w = (const float*)d_in[3];
    const float* attn_b = (const float*)d_in[4];
    const float* proj_w = (const float*)d_in[5];
    const float* proj_b = (const float*)d_in[6];
    const float* ln2_w  = (const float*)d_in[7];
    const float* ln2_b  = (const float*)d_in[8];
    const float* fc_w   = (const float*)d_in[9];
    const float* fc_b   = (const float*)d_in[10];
    const float* fc2_w  = (const float*)d_in[11];
    const float* fc2_b  = (const float*)d_in[12];

    float *h;
    __half *y, *qkv, *att, *m1, *wqkvT, *wprojT, *wfcT, *wfc2T;
    cudaGetSymbolAddress((void**)&h,     g_h);
    cudaGetSymbolAddress((void**)&y,     g_y);
    cudaGetSymbolAddress((void**)&qkv,   g_qkv);
    cudaGetSymbolAddress((void**)&att,   g_att);
    cudaGetSymbolAddress((void**)&m1,    g_m1);
    cudaGetSymbolAddress((void**)&wqkvT, g_wqkvT);
    cudaGetSymbolAddress((void**)&wprojT,g_wprojT);
    cudaGetSymbolAddress((void**)&wfcT,  g_wfcT);
    cudaGetSymbolAddress((void**)&wfc2T, g_wfc2T);

    constexpr int SMEM_128 = 2 * (128 + 128) * 144;   // 73728 B
    constexpr int SMEM_64  = 2 * (128 +  64) * 144;   // 55296 B
    cudaFuncSetAttribute(mma_gemm<0,64>,  cudaFuncAttributeMaxDynamicSharedMemorySize, SMEM_64);
    cudaFuncSetAttribute(mma_gemm<1,128>, cudaFuncAttributeMaxDynamicSharedMemorySize, SMEM_128);
    cudaFuncSetAttribute(mma_gemm<2,64>,  cudaFuncAttributeMaxDynamicSharedMemorySize, SMEM_64);
    cudaFuncSetAttribute(flash_attn_tc,   cudaFuncAttributeMaxDynamicSharedMemorySize, ATT_SMEM);

    // PDL launcher on the default stream
    auto pdl = [](auto kern, dim3 grid, dim3 block, size_t smem, auto... args) {
        cudaLaunchConfig_t cfg = {};
        cfg.gridDim = grid; cfg.blockDim = block;
        cfg.dynamicSmemBytes = smem; cfg.stream = 0;
        cudaLaunchAttribute attr[1];
        attr[0].id = cudaLaunchAttributeProgrammaticStreamSerialization;
        attr[0].val.programmaticStreamSerializationAllowed = 1;
        cfg.attrs = attr; cfg.numAttrs = 1;
        cudaLaunchKernelEx(&cfg, kern, args...);
    };

    // ---- side stream: weight transposes overlap layer-0 compute -------------
    cudaStream_t s2;
    cudaStreamCreateWithFlags(&s2, cudaStreamNonBlocking);
    cudaEvent_t evFork, evW0, evW1;
    cudaEventCreateWithFlags(&evFork, cudaEventDisableTiming);
    cudaEventCreateWithFlags(&evW0,   cudaEventDisableTiming);
    cudaEventCreateWithFlags(&evW1,   cudaEventDisableTiming);

    cudaEventRecord(evFork, 0);
    cudaStreamWaitEvent(s2, evFork, 0);

    const dim3 tb(32, 8);
    transpose_half_kernel<<<dim3(3*EE/32, EE/32, NL),   tb, 0, s2>>>(attn_w, wqkvT,  EE,   3*EE);
    cudaEventRecord(evW0, s2);                         // qkv weights ready
    transpose_half_kernel<<<dim3(EE/32,   EE/32, NL),   tb, 0, s2>>>(proj_w, wprojT, EE,   EE);
    transpose_half_kernel<<<dim3(4*EE/32, EE/32, NL),   tb, 0, s2>>>(fc_w,   wfcT,   EE,   4*EE);
    transpose_half_kernel<<<dim3(EE/32,   4*EE/32, NL), tb, 0, s2>>>(fc2_w,  wfc2T,  4*EE, EE);
    cudaEventRecord(evW1, s2);                         // all other weights ready

    cudaMemcpyAsync(h, x, (size_t)TT * EE * sizeof(float),
                    cudaMemcpyDeviceToDevice, 0);

    const dim3 blkG(128);                      // GEMM CTAs: 4 warps
    const dim3 blkA(128);                      // attention CTAs: 4 warps
    const dim3 blk(256);
    const dim3 gLN(TT);
    const dim3 gQKV(3 * EE / 64, TT / 128);    // (48,16) = 768 CTAs
    const dim3 gPROJ(EE / 64, TT / 128);       // (16,16)
    const dim3 gFC(4 * EE / 128, TT / 128);    // (32,16)
    const dim3 gFC2(EE / 64, TT / 128);        // (16,16)
    const dim3 gATT(TT / BQ, NH);              // (32,16) = 512 CTAs

    for (int lyr = 0; lyr < NL; lyr++) {
        const __half* aw  = wqkvT  + (size_t)lyr * EE * 3 * EE;
        const float*  ab  = attn_b + (size_t)lyr * 3 * EE;
        const __half* pw  = wprojT + (size_t)lyr * EE * EE;
        const float*  pb  = proj_b + (size_t)lyr * EE;
        const __half* fw  = wfcT   + (size_t)lyr * EE * 4 * EE;
        const float*  fb  = fc_b   + (size_t)lyr * 4 * EE;
        const __half* f2w = wfc2T  + (size_t)lyr * 4 * EE * EE;
        const float*  f2b = fc2_b  + (size_t)lyr * EE;

        // attn block
        pdl(ln_kernel, gLN, blk, 0,
            (const float*)h, (const float*)(ln1_w + (size_t)lyr * EE),
            (const float*)(ln1_b + (size_t)lyr * EE), (__half*)y);
        if (lyr == 0) cudaStreamWaitEvent(0, evW0, 0);          // wqkvT ready
        pdl(mma_gemm<0,64>, gQKV, blkG, (size_t)SMEM_64,
            (const __half*)y, aw, ab, (void*)qkv, (const float*)nullptr,
            (int)TT, (int)(3*EE), (int)EE);
        pdl(flash_attn_tc, gATT, blkA, (size_t)ATT_SMEM,
            (const __half*)qkv, (__half*)att);
        if (lyr == 0) cudaStreamWaitEvent(0, evW1, 0);          // remaining weights ready
        pdl(mma_gemm<2,64>, gPROJ, blkG, (size_t)SMEM_64,
            (const __half*)att, pw, pb, (void*)h, (const float*)h,
            (int)TT, (int)EE, (int)EE);

        // MLP block
        pdl(ln_kernel, gLN, blk, 0,
            (const float*)h, (const float*)(ln2_w + (size_t)lyr * EE),
            (const float*)(ln2_b + (size_t)lyr * EE), (__half*)y);
        pdl(mma_gemm<1,128>, gFC, blkG, (size_t)SMEM_128,
            (const __half*)y, fw, fb, (void*)m1, (const float*)nullptr,
            (int)TT, (int)(4*EE), (int)EE);
        // final layer: write residual result straight into d_out (fp32)
        float* c_out = (lyr == NL - 1) ? (float*)d_out : h;
        pdl(mma_gemm<2,64>, gFC2, blkG, (size_t)SMEM_64,
            (const __half*)m1, f2w, f2b, (void*)c_out, (const float*)h,
            (int)TT, (int)EE, (int)(4*EE));
    }
}